// round 2
// baseline (speedup 1.0000x reference)
#include <cuda_runtime.h>
#include <cuda_bf16.h>

#define BB 4
#define SS 512
#define EE 512
#define UU 256

// Scratch (__device__ globals, allocation-free rule)
__device__ float g_K[BB * SS * UU];   // key_pre + b1
__device__ float g_Q[BB * SS * UU];   // qry_pre
__device__ float g_S[BB * SS * SS];   // scores -> probs (in place)

typedef unsigned long long u64;

__device__ __forceinline__ u64 pack2(float x, float y) {
    u64 r; asm("mov.b64 %0,{%1,%2};" : "=l"(r) : "f"(x), "f"(y)); return r;
}
__device__ __forceinline__ u64 fma2(u64 a, u64 b, u64 c) {
    u64 d; asm("fma.rn.f32x2 %0,%1,%2,%3;" : "=l"(d) : "l"(a), "l"(b), "l"(c)); return d;
}
__device__ __forceinline__ float2 unpack2(u64 v) {
    float2 f; asm("mov.b64 {%0,%1},%2;" : "=f"(f.x), "=f"(f.y) : "l"(v)); return f;
}
__device__ __forceinline__ float tanh_ap(float x) {
    float y; asm("tanh.approx.f32 %0,%1;" : "=f"(y) : "f"(x)); return y;
}
__device__ __forceinline__ float ex2_ap(float x) {
    float y; asm("ex2.approx.f32 %0,%1;" : "=f"(y) : "f"(x)); return y;
}
__device__ __forceinline__ void cp16(void* dst, const void* src) {
    unsigned d = (unsigned)__cvta_generic_to_shared(dst);
    asm volatile("cp.async.ca.shared.global [%0],[%1],16;" :: "r"(d), "l"(src) : "memory");
}

// ---------------------------------------------------------------------------
// 64(M) x 128(N) tile SGEMM, BK=16, 256 threads, 4x8 micro-tile, f32x2 FFMA2.
// A stored DUPLICATED in smem ((a,a) pairs) so the inner loop is pure
// LDS.128 + FFMA2 (no packing movs). Double-buffered smem.
// ---------------------------------------------------------------------------
__device__ __forceinline__ void sgemm_64x128(
    const float* __restrict__ A, const float* __restrict__ B,
    float* __restrict__ C, const float* __restrict__ bias,
    int K, int lda, int ldb, int ldc)
{
    __shared__ __align__(16) float As2[2][16][132];  // [k][2*m] duplicated
    __shared__ __align__(16) float Bs[2][16][128];

    const int tid = threadIdx.x;
    const int tx = tid & 15;            // N micro (8 cols)
    const int ty = tid >> 4;            // M micro (4 rows)
    const int ar = tid >> 2;            // A load: row 0..63
    const int ak = (tid & 3) << 2;      // A load: k 0,4,8,12
    const int br = tid >> 4;            // B load: k row 0..15
    const int bc = (tid & 15) << 3;     // B load: col 0..120

    const int row0 = blockIdx.y * 64;
    const int col0 = blockIdx.x * 128;

    const float* Ap = A + (size_t)(row0 + ar) * lda + ak;
    const float* Bp = B + (size_t)br * ldb + col0 + bc;

    // stage 0
    float4 ra  = *(const float4*)Ap;
    float4 rb0 = *(const float4*)Bp;
    float4 rb1 = *(const float4*)(Bp + 4);
    *(u64*)&As2[0][ak + 0][ar * 2] = pack2(ra.x, ra.x);
    *(u64*)&As2[0][ak + 1][ar * 2] = pack2(ra.y, ra.y);
    *(u64*)&As2[0][ak + 2][ar * 2] = pack2(ra.z, ra.z);
    *(u64*)&As2[0][ak + 3][ar * 2] = pack2(ra.w, ra.w);
    *(float4*)&Bs[0][br][bc]     = rb0;
    *(float4*)&Bs[0][br][bc + 4] = rb1;
    __syncthreads();

    u64 acc[4][4];
#pragma unroll
    for (int i = 0; i < 4; i++)
#pragma unroll
        for (int j = 0; j < 4; j++) acc[i][j] = 0ull;

    int buf = 0;
    for (int k0 = 0; k0 < K; k0 += 16) {
        const bool more = (k0 + 16) < K;
        float4 na, nb0, nb1;
        if (more) {
            na  = *(const float4*)(Ap + k0 + 16);
            nb0 = *(const float4*)(Bp + (size_t)(k0 + 16) * ldb);
            nb1 = *(const float4*)(Bp + (size_t)(k0 + 16) * ldb + 4);
        }
#pragma unroll
        for (int kk = 0; kk < 16; kk++) {
            ulonglong2 aa0 = *(const ulonglong2*)&As2[buf][kk][ty * 8];
            ulonglong2 aa1 = *(const ulonglong2*)&As2[buf][kk][ty * 8 + 4];
            ulonglong2 bb0 = *(const ulonglong2*)&Bs[buf][kk][tx * 8];
            ulonglong2 bb1 = *(const ulonglong2*)&Bs[buf][kk][tx * 8 + 4];
            acc[0][0] = fma2(aa0.x, bb0.x, acc[0][0]);
            acc[0][1] = fma2(aa0.x, bb0.y, acc[0][1]);
            acc[0][2] = fma2(aa0.x, bb1.x, acc[0][2]);
            acc[0][3] = fma2(aa0.x, bb1.y, acc[0][3]);
            acc[1][0] = fma2(aa0.y, bb0.x, acc[1][0]);
            acc[1][1] = fma2(aa0.y, bb0.y, acc[1][1]);
            acc[1][2] = fma2(aa0.y, bb1.x, acc[1][2]);
            acc[1][3] = fma2(aa0.y, bb1.y, acc[1][3]);
            acc[2][0] = fma2(aa1.x, bb0.x, acc[2][0]);
            acc[2][1] = fma2(aa1.x, bb0.y, acc[2][1]);
            acc[2][2] = fma2(aa1.x, bb1.x, acc[2][2]);
            acc[2][3] = fma2(aa1.x, bb1.y, acc[2][3]);
            acc[3][0] = fma2(aa1.y, bb0.x, acc[3][0]);
            acc[3][1] = fma2(aa1.y, bb0.y, acc[3][1]);
            acc[3][2] = fma2(aa1.y, bb1.x, acc[3][2]);
            acc[3][3] = fma2(aa1.y, bb1.y, acc[3][3]);
        }
        __syncthreads();
        if (more) {
            const int nb = buf ^ 1;
            *(u64*)&As2[nb][ak + 0][ar * 2] = pack2(na.x, na.x);
            *(u64*)&As2[nb][ak + 1][ar * 2] = pack2(na.y, na.y);
            *(u64*)&As2[nb][ak + 2][ar * 2] = pack2(na.z, na.z);
            *(u64*)&As2[nb][ak + 3][ar * 2] = pack2(na.w, na.w);
            *(float4*)&Bs[nb][br][bc]     = nb0;
            *(float4*)&Bs[nb][br][bc + 4] = nb1;
            buf = nb;
            __syncthreads();
        }
    }

    const int orow = row0 + ty * 4;
    const int ocol = col0 + tx * 8;
    float4 bv0 = make_float4(0.f, 0.f, 0.f, 0.f);
    float4 bv1 = make_float4(0.f, 0.f, 0.f, 0.f);
    if (bias) {
        bv0 = *(const float4*)(bias + ocol);
        bv1 = *(const float4*)(bias + ocol + 4);
    }
#pragma unroll
    for (int i = 0; i < 4; i++) {
        float2 c0 = unpack2(acc[i][0]);
        float2 c1 = unpack2(acc[i][1]);
        float2 c2 = unpack2(acc[i][2]);
        float2 c3 = unpack2(acc[i][3]);
        float4 o0 = make_float4(c0.x + bv0.x, c0.y + bv0.y, c1.x + bv0.z, c1.y + bv0.w);
        float4 o1 = make_float4(c2.x + bv1.x, c2.y + bv1.y, c3.x + bv1.z, c3.y + bv1.w);
        float* cp = C + (size_t)(orow + i) * ldc + ocol;
        *(float4*)cp       = o0;
        *(float4*)(cp + 4) = o1;
    }
}

// Stage 1: K = h1 @ w[:E] + b1 (z=0); Q = h2 @ w[E:] (z=1)
// grid (256/128=2, 2048/64=32, 2), block 256
__global__ void qk_gemm(const float* __restrict__ h1, const float* __restrict__ h2,
                        const float* __restrict__ w, const float* __restrict__ b1)
{
    const int z = blockIdx.z;
    const float* A  = z ? h2 : h1;
    const float* Bm = w + (size_t)z * EE * UU;
    float* C = z ? g_Q : g_K;
    sgemm_64x128(A, Bm, C, z ? nullptr : b1, EE, EE, UU, UU);
}

// Stage 4: out[b] = P[b] @ h1[b], grid (512/128=4, 512/64=8, 4)
__global__ void pv_gemm(const float* __restrict__ h1, float* __restrict__ out)
{
    const int b = blockIdx.z;
    sgemm_64x128(g_S + (size_t)b * SS * SS, h1 + (size_t)b * SS * EE,
                 out + (size_t)b * SS * EE, nullptr, SS, SS, EE, EE);
}

// ---------------------------------------------------------------------------
// Fused scores + softmax. CTA = 8 query rows x full 512 keys, one batch.
// Warp w owns row it*8+w; lane jl owns key column within each 32-wide chunk.
// K tiles streamed via cp.async double buffer; stages = (jc 0..15) x (uc 0..1).
// b2 dropped: softmax(s + const) == softmax(s).
// grid (64, 4), block 256.
// ---------------------------------------------------------------------------
__global__ void scores_softmax(const float* __restrict__ v)
{
    __shared__ __align__(16) float4 qs[8][64];      // Q rows (u as float4)
    __shared__ __align__(16) float4 vs[64];         // v
    __shared__ __align__(16) float4 ks[2][32][33];  // K chunk, padded rows

    const int it = blockIdx.x;
    const int b  = blockIdx.y;
    const int tid = threadIdx.x;
    const int w  = tid >> 5;
    const int jl = tid & 31;

    const float4* Q4 = (const float4*)g_Q + (size_t)(b * SS + it * 8) * 64;
    const float4* K4 = (const float4*)g_K + (size_t)(b * SS) * 64;

    // load Q tile (contiguous 512 float4s) and v
    ((float4*)qs)[tid]       = Q4[tid];
    ((float4*)qs)[tid + 256] = Q4[tid + 256];
    if (tid < 64) vs[tid] = ((const float4*)v)[tid];

    const int lc = tid & 31;        // load col (float4)
    const int lr = (tid >> 5) * 4;  // load row base

    // prefetch stage 0 (jc=0, uc=0) into ks[0]
#pragma unroll
    for (int i = 0; i < 4; i++)
        cp16(&ks[0][lr + i][lc], K4 + (size_t)(lr + i) * 64 + lc);
    asm volatile("cp.async.commit_group;");

    float* prow = g_S + (size_t)(b * SS + it * 8 + w) * SS + jl;
    float m = -1e30f;

#pragma unroll 1
    for (int s = 0; s < 32; s++) {
        if (s < 31) {
            const int s1 = s + 1;
            const int jc1 = s1 >> 1, uc1 = s1 & 1, nb = s1 & 1;
#pragma unroll
            for (int i = 0; i < 4; i++)
                cp16(&ks[nb][lr + i][lc],
                     K4 + (size_t)(jc1 * 32 + lr + i) * 64 + uc1 * 32 + lc);
            asm volatile("cp.async.commit_group;");
            asm volatile("cp.async.wait_group 1;");
        } else {
            asm volatile("cp.async.wait_group 0;");
        }
        __syncthreads();

        const int jc = s >> 1, uc = s & 1;
        const float4* kp = &ks[s & 1][jl][0];
        const float4* qp = &qs[w][uc * 32];
        const float4* vp = &vs[uc * 32];
        float ax = 0.f, ay = 0.f, az = 0.f, aw = 0.f;
#pragma unroll
        for (int cc = 0; cc < 32; cc++) {
            const float4 kv = kp[cc];
            const float4 qv = qp[cc];
            const float4 vv = vp[cc];
            ax += vv.x * tanh_ap(qv.x + kv.x);
            ay += vv.y * tanh_ap(qv.y + kv.y);
            az += vv.z * tanh_ap(qv.z + kv.z);
            aw += vv.w * tanh_ap(qv.w + kv.w);
        }
        if (uc == 0) {
            // stash partial for this jc in the score slot (completed next stage)
            prow[jc * 32] = (ax + ay) + (az + aw);
        } else {
            const float a = prow[jc * 32] + (ax + ay) + (az + aw);
            prow[jc * 32] = a;
            m = fmaxf(m, a);
        }
        __syncthreads();
    }

    // row max across warp (row's 512 scores live across 32 lanes x 16 slots)
#pragma unroll
    for (int o = 16; o > 0; o >>= 1)
        m = fmaxf(m, __shfl_xor_sync(0xffffffffu, m, o));

    const float L2E = 1.4426950408889634f;
    float sum = 0.f;
#pragma unroll
    for (int jc = 0; jc < 16; jc++)
        sum += ex2_ap((prow[jc * 32] - m) * L2E);
#pragma unroll
    for (int o = 16; o > 0; o >>= 1)
        sum += __shfl_xor_sync(0xffffffffu, sum, o);

    const float inv = 1.0f / sum;
#pragma unroll
    for (int jc = 0; jc < 16; jc++)
        prow[jc * 32] = ex2_ap((prow[jc * 32] - m) * L2E) * inv;
}

extern "C" void kernel_launch(void* const* d_in, const int* in_sizes, int n_in,
                              void* d_out, int out_size)
{
    const float* h1 = (const float*)d_in[0];
    const float* h2 = (const float*)d_in[1];
    const float* w  = (const float*)d_in[2];
    const float* b1 = (const float*)d_in[3];
    const float* v  = (const float*)d_in[4];
    // b2 (d_in[5]) intentionally unused: softmax is shift-invariant.
    float* out = (float*)d_out;

    dim3 gA(UU / 128, (BB * SS) / 64, 2);    // (2, 32, 2) = 128 CTAs
    qk_gemm<<<gA, 256>>>(h1, h2, w, b1);

    dim3 gB(SS / 8, BB);                     // (64, 4) = 256 CTAs
    scores_softmax<<<gB, 256>>>(v);

    dim3 gD(EE / 128, SS / 64, BB);          // (4, 8, 4) = 128 CTAs
    pv_gemm<<<gD, 256>>>(h1, out);
}

// round 3
// speedup vs baseline: 1.1233x; 1.1233x over previous
#include <cuda_runtime.h>
#include <cuda_bf16.h>

#define BB 4
#define SS 512
#define EE 512
#define UU 256

// Scratch (__device__ globals, allocation-free rule)
__device__ float g_K[BB * SS * UU];   // key_pre + b1
__device__ float g_Q[BB * SS * UU];   // qry_pre
__device__ float g_S[BB * SS * SS];   // softmax probs

typedef unsigned long long u64;

__device__ __forceinline__ u64 pack2(float x, float y) {
    u64 r; asm("mov.b64 %0,{%1,%2};" : "=l"(r) : "f"(x), "f"(y)); return r;
}
__device__ __forceinline__ u64 fma2(u64 a, u64 b, u64 c) {
    u64 d; asm("fma.rn.f32x2 %0,%1,%2,%3;" : "=l"(d) : "l"(a), "l"(b), "l"(c)); return d;
}
__device__ __forceinline__ float2 unpack2(u64 v) {
    float2 f; asm("mov.b64 {%0,%1},%2;" : "=f"(f.x), "=f"(f.y) : "l"(v)); return f;
}
__device__ __forceinline__ float tanh_ap(float x) {
    float y; asm("tanh.approx.f32 %0,%1;" : "=f"(y) : "f"(x)); return y;
}
__device__ __forceinline__ float ex2_ap(float x) {
    float y; asm("ex2.approx.f32 %0,%1;" : "=f"(y) : "f"(x)); return y;
}
__device__ __forceinline__ void cp16(void* dst, const void* src) {
    unsigned d = (unsigned)__cvta_generic_to_shared(dst);
    asm volatile("cp.async.ca.shared.global [%0],[%1],16;" :: "r"(d), "l"(src) : "memory");
}

// ---------------------------------------------------------------------------
// 64x64 tile SGEMM, BK=16, 128 threads, 8(M)x4(N) micro-tile, FFMA2.
// A duplicated in smem as (a,a) u64 pairs; inner loop = 5 LDS.128 + 16 FFMA2
// per thread per kk (A/B smem reads are warp-broadcast heavy -> FMA-bound).
// Register-prefetch pipeline (gmem loads for next K-block issued before the
// compute of the current one).
// ---------------------------------------------------------------------------
__device__ __forceinline__ void sgemm_64x64_f2(
    const float* __restrict__ A, const float* __restrict__ B,
    float* __restrict__ C, const float* __restrict__ bias,
    int K, int lda, int ldb, int ldc)
{
    __shared__ __align__(16) float As2[16][128];  // [k][2*m] duplicated
    __shared__ __align__(16) float Bs[16][64];

    const int tid = threadIdx.x;
    const int tx = tid & 15;          // N micro (4 cols)
    const int ty = tid >> 4;          // M micro (8 rows)

    // A loads: thread -> row = tid>>1, k cols (tid&1)*8 + {0..3, 4..7}
    const int ar = tid >> 1;
    const int ak = (tid & 1) * 8;
    // B loads: idx = tid and tid+128 -> br = idx>>4, bc = (idx&15)*4
    const int br = tid >> 4;          // 0..7 (and +8)
    const int bc = (tid & 15) * 4;

    const int row0 = blockIdx.y * 64;
    const int col0 = blockIdx.x * 64;

    const float* Ap = A + (size_t)(row0 + ar) * lda + ak;
    const float* Bp = B + (size_t)br * ldb + col0 + bc;
    const size_t ldb8 = (size_t)8 * ldb;

    // prefetch block 0
    float4 pa0 = *(const float4*)Ap;
    float4 pa1 = *(const float4*)(Ap + 4);
    float4 pb0 = *(const float4*)Bp;
    float4 pb1 = *(const float4*)(Bp + ldb8);

    u64 acc[8][2];
#pragma unroll
    for (int i = 0; i < 8; i++) { acc[i][0] = 0ull; acc[i][1] = 0ull; }

    for (int k0 = 0; k0 < K; k0 += 16) {
        // store current block to smem
        *(u64*)&As2[ak + 0][ar * 2] = pack2(pa0.x, pa0.x);
        *(u64*)&As2[ak + 1][ar * 2] = pack2(pa0.y, pa0.y);
        *(u64*)&As2[ak + 2][ar * 2] = pack2(pa0.z, pa0.z);
        *(u64*)&As2[ak + 3][ar * 2] = pack2(pa0.w, pa0.w);
        *(u64*)&As2[ak + 4][ar * 2] = pack2(pa1.x, pa1.x);
        *(u64*)&As2[ak + 5][ar * 2] = pack2(pa1.y, pa1.y);
        *(u64*)&As2[ak + 6][ar * 2] = pack2(pa1.z, pa1.z);
        *(u64*)&As2[ak + 7][ar * 2] = pack2(pa1.w, pa1.w);
        *(float4*)&Bs[br][bc]     = pb0;
        *(float4*)&Bs[br + 8][bc] = pb1;
        __syncthreads();

        // issue gmem loads for next block (latency hidden by compute)
        const bool more = (k0 + 16) < K;
        if (more) {
            const float* Ap2 = Ap + k0 + 16;
            const float* Bp2 = Bp + (size_t)(k0 + 16) * ldb;
            pa0 = *(const float4*)Ap2;
            pa1 = *(const float4*)(Ap2 + 4);
            pb0 = *(const float4*)Bp2;
            pb1 = *(const float4*)(Bp2 + ldb8);
        }

#pragma unroll
        for (int kk = 0; kk < 16; kk++) {
            const ulonglong2 b01 = *(const ulonglong2*)&Bs[kk][tx * 4];
#pragma unroll
            for (int mp = 0; mp < 4; mp++) {
                const ulonglong2 a2 = *(const ulonglong2*)&As2[kk][ty * 16 + mp * 4];
                acc[2 * mp + 0][0] = fma2(a2.x, b01.x, acc[2 * mp + 0][0]);
                acc[2 * mp + 0][1] = fma2(a2.x, b01.y, acc[2 * mp + 0][1]);
                acc[2 * mp + 1][0] = fma2(a2.y, b01.x, acc[2 * mp + 1][0]);
                acc[2 * mp + 1][1] = fma2(a2.y, b01.y, acc[2 * mp + 1][1]);
            }
        }
        __syncthreads();
    }

    const int orow = row0 + ty * 8;
    const int ocol = col0 + tx * 4;
    float4 bv = make_float4(0.f, 0.f, 0.f, 0.f);
    if (bias) bv = *(const float4*)(bias + ocol);
#pragma unroll
    for (int m = 0; m < 8; m++) {
        const float2 c01 = unpack2(acc[m][0]);
        const float2 c23 = unpack2(acc[m][1]);
        float4 o = make_float4(c01.x + bv.x, c01.y + bv.y, c23.x + bv.z, c23.y + bv.w);
        *(float4*)&C[(size_t)(orow + m) * ldc + ocol] = o;
    }
}

// Stage 1: K = h1 @ w[:E] + b1 (z=0); Q = h2 @ w[E:] (z=1)
// grid (256/64=4, 2048/64=32, 2) = 256 CTAs, block 128
__global__ void __launch_bounds__(128)
qk_gemm(const float* __restrict__ h1, const float* __restrict__ h2,
        const float* __restrict__ w, const float* __restrict__ b1)
{
    const int z = blockIdx.z;
    const float* A  = z ? h2 : h1;
    const float* Bm = w + (size_t)z * EE * UU;
    float* C = z ? g_Q : g_K;
    sgemm_64x64_f2(A, Bm, C, z ? nullptr : b1, EE, EE, UU, UU);
}

// Stage 3: out[b] = P[b] @ h1[b], grid (8, 8, 4) = 256 CTAs, block 128
__global__ void __launch_bounds__(128)
pv_gemm(const float* __restrict__ h1, float* __restrict__ out)
{
    const int b = blockIdx.z;
    sgemm_64x64_f2(g_S + (size_t)b * SS * SS, h1 + (size_t)b * SS * EE,
                   out + (size_t)b * SS * EE, nullptr, SS, SS, EE, EE);
}

// ---------------------------------------------------------------------------
// Fused scores + softmax, fully register-resident scores.
// CTA = 8 query rows x all 512 keys, one batch. Warp w owns query row
// it*8+w; lane jl owns key column jl within each of 16 j-chunks; the 16
// chunk-accumulators live in registers across both u-halves.
// Stages s = uc*16 + jc (uc = u-half, jc = 32-key chunk); K chunk tiles are
// streamed with a race-free 2-deep cp.async double buffer.
// b2 dropped (softmax shift-invariance). grid (64, 4), block 256.
// ---------------------------------------------------------------------------
__global__ void __launch_bounds__(256)
scores_softmax(const float* __restrict__ v)
{
    __shared__ __align__(16) float4 qs[8][64];      // Q rows
    __shared__ __align__(16) float4 vs[64];         // v
    __shared__ __align__(16) float4 ks[2][32][33];  // K chunk (padded)

    const int it = blockIdx.x;
    const int b  = blockIdx.y;
    const int tid = threadIdx.x;
    const int w  = tid >> 5;
    const int jl = tid & 31;

    const float4* Q4 = (const float4*)g_Q + (size_t)(b * SS + it * 8) * 64;
    const float4* K4 = (const float4*)g_K + (size_t)(b * SS) * 64;

    ((float4*)qs)[tid]       = Q4[tid];
    ((float4*)qs)[tid + 256] = Q4[tid + 256];
    if (tid < 64) vs[tid] = ((const float4*)v)[tid];

    const int lc = tid & 31;        // load col (float4)
    const int lr = (tid >> 5) * 4;  // load row base

    // issue stages 0 and 1 (two groups in flight)
#pragma unroll
    for (int i = 0; i < 4; i++)
        cp16(&ks[0][lr + i][lc], K4 + (size_t)(lr + i) * 64 + lc);
    asm volatile("cp.async.commit_group;");
#pragma unroll
    for (int i = 0; i < 4; i++)   // stage 1: uc=0, jc=1
        cp16(&ks[1][lr + i][lc], K4 + (size_t)(32 + lr + i) * 64 + lc);
    asm volatile("cp.async.commit_group;");

    float acc[16];
#pragma unroll
    for (int i = 0; i < 16; i++) acc[i] = 0.f;

#pragma unroll 1
    for (int s = 0; s < 32; s++) {
        if (s < 31) { asm volatile("cp.async.wait_group 1;"); }
        else        { asm volatile("cp.async.wait_group 0;"); }
        __syncthreads();

        const int uc = s >> 4, jc = s & 15;
        const float4* kp = &ks[s & 1][jl][0];
        const float4* qp = &qs[w][uc * 32];
        const float4* vp = &vs[uc * 32];
        float ax = 0.f, ay = 0.f, az = 0.f, aw = 0.f;
#pragma unroll
        for (int cc = 0; cc < 32; cc++) {
            const float4 kv = kp[cc];
            const float4 qv = qp[cc];
            const float4 vv = vp[cc];
            ax += vv.x * tanh_ap(qv.x + kv.x);
            ay += vv.y * tanh_ap(qv.y + kv.y);
            az += vv.z * tanh_ap(qv.z + kv.z);
            aw += vv.w * tanh_ap(qv.w + kv.w);
        }
        acc[jc] += (ax + ay) + (az + aw);
        __syncthreads();   // everyone done reading ks[s&1] before refill

        if (s < 30) {
            const int s2 = s + 2;
            const int jc2 = s2 & 15, uc2 = s2 >> 4;
#pragma unroll
            for (int i = 0; i < 4; i++)
                cp16(&ks[s & 1][lr + i][lc],
                     K4 + (size_t)(jc2 * 32 + lr + i) * 64 + uc2 * 32 + lc);
            asm volatile("cp.async.commit_group;");
        }
    }

    // softmax over the row (16 reg slots x 32 lanes = 512 keys)
    float m = acc[0];
#pragma unroll
    for (int i = 1; i < 16; i++) m = fmaxf(m, acc[i]);
#pragma unroll
    for (int o = 16; o > 0; o >>= 1)
        m = fmaxf(m, __shfl_xor_sync(0xffffffffu, m, o));

    const float L2E = 1.4426950408889634f;
    float sum = 0.f;
#pragma unroll
    for (int i = 0; i < 16; i++) {
        acc[i] = ex2_ap((acc[i] - m) * L2E);
        sum += acc[i];
    }
#pragma unroll
    for (int o = 16; o > 0; o >>= 1)
        sum += __shfl_xor_sync(0xffffffffu, sum, o);
    const float inv = 1.0f / sum;

    float* prow = g_S + (size_t)(b * SS + it * 8 + w) * SS + jl;
#pragma unroll
    for (int jc = 0; jc < 16; jc++)
        prow[jc * 32] = acc[jc] * inv;
}

extern "C" void kernel_launch(void* const* d_in, const int* in_sizes, int n_in,
                              void* d_out, int out_size)
{
    const float* h1 = (const float*)d_in[0];
    const float* h2 = (const float*)d_in[1];
    const float* w  = (const float*)d_in[2];
    const float* b1 = (const float*)d_in[3];
    const float* v  = (const float*)d_in[4];
    // b2 (d_in[5]) unused: softmax is shift-invariant.
    float* out = (float*)d_out;

    dim3 gA(UU / 64, (BB * SS) / 64, 2);     // (4, 32, 2) = 256 CTAs
    qk_gemm<<<gA, 128>>>(h1, h2, w, b1);

    dim3 gB(SS / 8, BB);                     // (64, 4) = 256 CTAs
    scores_softmax<<<gB, 256>>>(v);

    dim3 gD(EE / 64, SS / 64, BB);           // (8, 8, 4) = 256 CTAs
    pv_gemm<<<gD, 128>>>(h1, out);
}

// round 4
// speedup vs baseline: 1.1382x; 1.0133x over previous
#include <cuda_runtime.h>
#include <cuda_bf16.h>

#define BB 4
#define SS 512
#define EE 512
#define UU 256
#define KSPLIT 4

// Scratch (__device__ globals, allocation-free rule)
__device__ float g_K[BB * SS * UU];            // key_pre + b1
__device__ float g_Q[BB * SS * UU];            // qry_pre
__device__ float g_S[BB * SS * SS];            // softmax probs
__device__ float g_part[KSPLIT * 2048 * 512];  // 16MB split-K partials (shared qk/pv)

typedef unsigned long long u64;

__device__ __forceinline__ u64 pack2(float x, float y) {
    u64 r; asm("mov.b64 %0,{%1,%2};" : "=l"(r) : "f"(x), "f"(y)); return r;
}
__device__ __forceinline__ u64 fma2(u64 a, u64 b, u64 c) {
    u64 d; asm("fma.rn.f32x2 %0,%1,%2,%3;" : "=l"(d) : "l"(a), "l"(b), "l"(c)); return d;
}
__device__ __forceinline__ float2 unpack2(u64 v) {
    float2 f; asm("mov.b64 {%0,%1},%2;" : "=f"(f.x), "=f"(f.y) : "l"(v)); return f;
}
__device__ __forceinline__ float tanh_ap(float x) {
    float y; asm("tanh.approx.f32 %0,%1;" : "=f"(y) : "f"(x)); return y;
}
__device__ __forceinline__ float ex2_ap(float x) {
    float y; asm("ex2.approx.f32 %0,%1;" : "=f"(y) : "f"(x)); return y;
}
__device__ __forceinline__ void cp16(void* dst, const void* src) {
    unsigned d = (unsigned)__cvta_generic_to_shared(dst);
    asm volatile("cp.async.ca.shared.global [%0],[%1],16;" :: "r"(d), "l"(src) : "memory");
}

// ---------------------------------------------------------------------------
// 64x64 tile x K=128 chunk SGEMM body. 128 threads, 8(M)x4(N) micro, FFMA2.
// A duplicated in smem as (a,a) pairs; register-prefetch pipeline.
// Writes the 64x64 result tile to P (partial buffer, ldp leading dim).
// ---------------------------------------------------------------------------
__device__ __forceinline__ void sgemm_64x64_k128(
    const float* __restrict__ A, const float* __restrict__ B,
    float* __restrict__ P, int lda, int ldb, int ldp,
    int row0, int col0)
{
    __shared__ __align__(16) float As2[16][128];  // [k][2*m] duplicated
    __shared__ __align__(16) float Bs[16][64];

    const int tid = threadIdx.x;
    const int tx = tid & 15;          // N micro (4 cols)
    const int ty = tid >> 4;          // M micro (8 rows)
    const int ar = tid >> 1;          // A load row 0..63
    const int ak = (tid & 1) * 8;     // A load k base
    const int br = tid >> 4;          // B load k row (and +8)
    const int bc = (tid & 15) * 4;    // B load col

    const float* Ap = A + (size_t)(row0 + ar) * lda + ak;
    const float* Bp = B + (size_t)br * ldb + col0 + bc;
    const size_t ldb8 = (size_t)8 * ldb;

    float4 pa0 = *(const float4*)Ap;
    float4 pa1 = *(const float4*)(Ap + 4);
    float4 pb0 = *(const float4*)Bp;
    float4 pb1 = *(const float4*)(Bp + ldb8);

    u64 acc[8][2];
#pragma unroll
    for (int i = 0; i < 8; i++) { acc[i][0] = 0ull; acc[i][1] = 0ull; }

#pragma unroll 1
    for (int k0 = 0; k0 < 128; k0 += 16) {
        *(u64*)&As2[ak + 0][ar * 2] = pack2(pa0.x, pa0.x);
        *(u64*)&As2[ak + 1][ar * 2] = pack2(pa0.y, pa0.y);
        *(u64*)&As2[ak + 2][ar * 2] = pack2(pa0.z, pa0.z);
        *(u64*)&As2[ak + 3][ar * 2] = pack2(pa0.w, pa0.w);
        *(u64*)&As2[ak + 4][ar * 2] = pack2(pa1.x, pa1.x);
        *(u64*)&As2[ak + 5][ar * 2] = pack2(pa1.y, pa1.y);
        *(u64*)&As2[ak + 6][ar * 2] = pack2(pa1.z, pa1.z);
        *(u64*)&As2[ak + 7][ar * 2] = pack2(pa1.w, pa1.w);
        *(float4*)&Bs[br][bc]     = pb0;
        *(float4*)&Bs[br + 8][bc] = pb1;
        __syncthreads();

        if (k0 + 16 < 128) {
            const float* Ap2 = Ap + k0 + 16;
            const float* Bp2 = Bp + (size_t)(k0 + 16) * ldb;
            pa0 = *(const float4*)Ap2;
            pa1 = *(const float4*)(Ap2 + 4);
            pb0 = *(const float4*)Bp2;
            pb1 = *(const float4*)(Bp2 + ldb8);
        }

#pragma unroll
        for (int kk = 0; kk < 16; kk++) {
            const ulonglong2 b01 = *(const ulonglong2*)&Bs[kk][tx * 4];
#pragma unroll
            for (int mp = 0; mp < 4; mp++) {
                const ulonglong2 a2 = *(const ulonglong2*)&As2[kk][ty * 16 + mp * 4];
                acc[2 * mp + 0][0] = fma2(a2.x, b01.x, acc[2 * mp + 0][0]);
                acc[2 * mp + 0][1] = fma2(a2.x, b01.y, acc[2 * mp + 0][1]);
                acc[2 * mp + 1][0] = fma2(a2.y, b01.x, acc[2 * mp + 1][0]);
                acc[2 * mp + 1][1] = fma2(a2.y, b01.y, acc[2 * mp + 1][1]);
            }
        }
        __syncthreads();
    }

    const int orow = row0 + ty * 8;
    const int ocol = col0 + tx * 4;
#pragma unroll
    for (int m = 0; m < 8; m++) {
        const float2 c01 = unpack2(acc[m][0]);
        const float2 c23 = unpack2(acc[m][1]);
        *(float4*)&P[(size_t)(orow + m) * ldp + ocol] =
            make_float4(c01.x, c01.y, c23.x, c23.y);
    }
}

// Stage 1a: split-K partials for K = h1@w1 (which=0) and Q = h2@w2 (which=1).
// grid (4, 32, 8=which*4+ks), block 128.  Partial slab (ks,which):
//   g_part + ((ks*2 + which) * 2048) * 256
__global__ void __launch_bounds__(128)
qk_gemm_split(const float* __restrict__ h1, const float* __restrict__ h2,
              const float* __restrict__ w)
{
    const int which = blockIdx.z >> 2;
    const int ks    = blockIdx.z & 3;
    const int k0    = ks * 128;
    const float* A  = (which ? h2 : h1) + k0;
    const float* Bm = w + (size_t)which * EE * UU + (size_t)k0 * UU;
    float* P = g_part + (size_t)(ks * 2 + which) * 2048 * 256;
    sgemm_64x64_k128(A, Bm, P, EE, UU, 256, blockIdx.y * 64, blockIdx.x * 64);
}

// Stage 1b: reduce partials -> g_K (+b1), g_Q. 262144 float4 slots.
// grid 1024, block 256.  t < 131072: K target; else Q.
__global__ void __launch_bounds__(256)
qk_reduce(const float* __restrict__ b1)
{
    const int t = blockIdx.x * 256 + threadIdx.x;
    const int which = t >> 17;               // 0: K, 1: Q
    const int i4 = t & 131071;               // float4 index within target
    const float4* p = (const float4*)g_part + (size_t)which * 131072 + i4;
    float4 s0 = p[0];
    float4 s1 = p[262144];                   // ks=1: offset 2*131072
    float4 s2 = p[524288];
    float4 s3 = p[786432];
    float4 o = make_float4((s0.x + s1.x) + (s2.x + s3.x),
                           (s0.y + s1.y) + (s2.y + s3.y),
                           (s0.z + s1.z) + (s2.z + s3.z),
                           (s0.w + s1.w) + (s2.w + s3.w));
    if (which == 0) {
        const float4 bv = ((const float4*)b1)[i4 & 63];   // col = (i4*4) % 256
        o.x += bv.x; o.y += bv.y; o.z += bv.z; o.w += bv.w;
        ((float4*)g_K)[i4] = o;
    } else {
        ((float4*)g_Q)[i4] = o;
    }
}

// Stage 3a: split-K partials for out[b] = P[b] @ h1[b].
// grid (8, 8, 16=b*4+ks), block 128. Partial slab ks: g_part + ks*2048*512,
// rows indexed b*512+row.
__global__ void __launch_bounds__(128)
pv_gemm_split(const float* __restrict__ h1)
{
    const int b  = blockIdx.z >> 2;
    const int ks = blockIdx.z & 3;
    const int k0 = ks * 128;
    const float* A  = g_S + (size_t)b * SS * SS + k0;
    const float* Bm = h1  + (size_t)b * SS * EE + (size_t)k0 * EE;
    float* P = g_part + (size_t)ks * 2048 * 512 + (size_t)b * 512 * 512;
    sgemm_64x64_k128(A, Bm, P, SS, EE, 512, blockIdx.y * 64, blockIdx.x * 64);
}

// Stage 3b: reduce partials -> out. 262144 float4 slots. grid 1024, block 256.
__global__ void __launch_bounds__(256)
pv_reduce(float* __restrict__ out)
{
    const int i4 = blockIdx.x * 256 + threadIdx.x;
    const float4* p = (const float4*)g_part + i4;
    float4 s0 = p[0];
    float4 s1 = p[262144];                   // ks stride = 2048*512/4
    float4 s2 = p[524288];
    float4 s3 = p[786432];
    ((float4*)out)[i4] = make_float4((s0.x + s1.x) + (s2.x + s3.x),
                                     (s0.y + s1.y) + (s2.y + s3.y),
                                     (s0.z + s1.z) + (s2.z + s3.z),
                                     (s0.w + s1.w) + (s2.w + s3.w));
}

// ---------------------------------------------------------------------------
// Stage 2: fused scores + softmax, register-resident (unchanged from R3).
// grid (64, 4), block 256.
// ---------------------------------------------------------------------------
__global__ void __launch_bounds__(256)
scores_softmax(const float* __restrict__ v)
{
    __shared__ __align__(16) float4 qs[8][64];
    __shared__ __align__(16) float4 vs[64];
    __shared__ __align__(16) float4 ks[2][32][33];

    const int it = blockIdx.x;
    const int b  = blockIdx.y;
    const int tid = threadIdx.x;
    const int w  = tid >> 5;
    const int jl = tid & 31;

    const float4* Q4 = (const float4*)g_Q + (size_t)(b * SS + it * 8) * 64;
    const float4* K4 = (const float4*)g_K + (size_t)(b * SS) * 64;

    ((float4*)qs)[tid]       = Q4[tid];
    ((float4*)qs)[tid + 256] = Q4[tid + 256];
    if (tid < 64) vs[tid] = ((const float4*)v)[tid];

    const int lc = tid & 31;
    const int lr = (tid >> 5) * 4;

#pragma unroll
    for (int i = 0; i < 4; i++)
        cp16(&ks[0][lr + i][lc], K4 + (size_t)(lr + i) * 64 + lc);
    asm volatile("cp.async.commit_group;");
#pragma unroll
    for (int i = 0; i < 4; i++)
        cp16(&ks[1][lr + i][lc], K4 + (size_t)(32 + lr + i) * 64 + lc);
    asm volatile("cp.async.commit_group;");

    float acc[16];
#pragma unroll
    for (int i = 0; i < 16; i++) acc[i] = 0.f;

#pragma unroll 1
    for (int s = 0; s < 32; s++) {
        if (s < 31) { asm volatile("cp.async.wait_group 1;"); }
        else        { asm volatile("cp.async.wait_group 0;"); }
        __syncthreads();

        const int uc = s >> 4, jc = s & 15;
        const float4* kp = &ks[s & 1][jl][0];
        const float4* qp = &qs[w][uc * 32];
        const float4* vp = &vs[uc * 32];
        float ax = 0.f, ay = 0.f, az = 0.f, aw = 0.f;
#pragma unroll
        for (int cc = 0; cc < 32; cc++) {
            const float4 kv = kp[cc];
            const float4 qv = qp[cc];
            const float4 vv = vp[cc];
            ax += vv.x * tanh_ap(qv.x + kv.x);
            ay += vv.y * tanh_ap(qv.y + kv.y);
            az += vv.z * tanh_ap(qv.z + kv.z);
            aw += vv.w * tanh_ap(qv.w + kv.w);
        }
        acc[jc] += (ax + ay) + (az + aw);
        __syncthreads();

        if (s < 30) {
            const int s2 = s + 2;
            const int jc2 = s2 & 15, uc2 = s2 >> 4;
#pragma unroll
            for (int i = 0; i < 4; i++)
                cp16(&ks[s & 1][lr + i][lc],
                     K4 + (size_t)(jc2 * 32 + lr + i) * 64 + uc2 * 32 + lc);
            asm volatile("cp.async.commit_group;");
        }
    }

    float m = acc[0];
#pragma unroll
    for (int i = 1; i < 16; i++) m = fmaxf(m, acc[i]);
#pragma unroll
    for (int o = 16; o > 0; o >>= 1)
        m = fmaxf(m, __shfl_xor_sync(0xffffffffu, m, o));

    const float L2E = 1.4426950408889634f;
    float sum = 0.f;
#pragma unroll
    for (int i = 0; i < 16; i++) {
        acc[i] = ex2_ap((acc[i] - m) * L2E);
        sum += acc[i];
    }
#pragma unroll
    for (int o = 16; o > 0; o >>= 1)
        sum += __shfl_xor_sync(0xffffffffu, sum, o);
    const float inv = 1.0f / sum;

    float* prow = g_S + (size_t)(b * SS + it * 8 + w) * SS + jl;
#pragma unroll
    for (int jc = 0; jc < 16; jc++)
        prow[jc * 32] = acc[jc] * inv;
}

extern "C" void kernel_launch(void* const* d_in, const int* in_sizes, int n_in,
                              void* d_out, int out_size)
{
    const float* h1 = (const float*)d_in[0];
    const float* h2 = (const float*)d_in[1];
    const float* w  = (const float*)d_in[2];
    const float* b1 = (const float*)d_in[3];
    const float* v  = (const float*)d_in[4];
    // b2 (d_in[5]) unused: softmax is shift-invariant.
    float* out = (float*)d_out;

    dim3 gA(UU / 64, (BB * SS) / 64, 2 * KSPLIT);   // (4, 32, 8) = 1024 CTAs
    qk_gemm_split<<<gA, 128>>>(h1, h2, w);
    qk_reduce<<<1024, 256>>>(b1);

    dim3 gB(SS / 8, BB);                            // (64, 4) = 256 CTAs
    scores_softmax<<<gB, 256>>>(v);

    dim3 gD(EE / 64, SS / 64, BB * KSPLIT);         // (8, 8, 16) = 1024 CTAs
    pv_gemm_split<<<gD, 128>>>(h1);
    pv_reduce<<<1024, 256>>>(out);
}

// round 5
// speedup vs baseline: 1.2031x; 1.0571x over previous
#include <cuda_runtime.h>
#include <cuda_bf16.h>

#define BB 4
#define SS 512
#define EE 512
#define UU 256
#define KSPLIT 4

// Scratch (__device__ globals, allocation-free rule)
__device__ float g_K[BB * SS * UU];            // key_pre + b1
__device__ float g_Q[BB * SS * UU];            // qry_pre
__device__ float g_S[BB * SS * SS];            // softmax probs
__device__ float g_part[KSPLIT * 2048 * 512];  // 16MB split-K partials (shared)

typedef unsigned long long u64;

__device__ __forceinline__ u64 pack2(float x, float y) {
    u64 r; asm("mov.b64 %0,{%1,%2};" : "=l"(r) : "f"(x), "f"(y)); return r;
}
__device__ __forceinline__ u64 fma2(u64 a, u64 b, u64 c) {
    u64 d; asm("fma.rn.f32x2 %0,%1,%2,%3;" : "=l"(d) : "l"(a), "l"(b), "l"(c)); return d;
}
__device__ __forceinline__ float2 unpack2(u64 v) {
    float2 f; asm("mov.b64 {%0,%1},%2;" : "=f"(f.x), "=f"(f.y) : "l"(v)); return f;
}
__device__ __forceinline__ float tanh_ap(float x) {
    float y; asm("tanh.approx.f32 %0,%1;" : "=f"(y) : "f"(x)); return y;
}
__device__ __forceinline__ float ex2_ap(float x) {
    float y; asm("ex2.approx.f32 %0,%1;" : "=f"(y) : "f"(x)); return y;
}
__device__ __forceinline__ void cp16(void* dst, const void* src) {
    unsigned d = (unsigned)__cvta_generic_to_shared(dst);
    asm volatile("cp.async.ca.shared.global [%0],[%1],16;" :: "r"(d), "l"(src) : "memory");
}

// ---------------------------------------------------------------------------
// 64(M) x 128(N) tile x K=128 chunk SGEMM. 128 threads, 8x8 micro, FFMA2 with
// M-packed accumulators: A smem pairs are natural (no duplication); B scalars
// duplicated to (b,b) via 1 mov each (ALU pipe, idle). 1.0 smem bytes/MAC.
// BK=8, register-prefetch pipeline.
// ---------------------------------------------------------------------------
__device__ __forceinline__ void sgemm_64x128_k128(
    const float* __restrict__ A, const float* __restrict__ B,
    float* __restrict__ P, int lda, int ldb, int ldp,
    int row0, int col0)
{
    __shared__ __align__(16) float As[8][64];    // [k][m]
    __shared__ __align__(16) float Bs[8][128];   // [k][n]

    const int tid = threadIdx.x;
    const int tx = tid & 15;          // N micro group (8 cols)
    const int ty = tid >> 4;          // M micro group (8 rows)
    const int ar = tid >> 1;          // A load: m row 0..63
    const int ak = (tid & 1) * 4;     // A load: k base 0/4
    const int br = tid >> 4;          // B load: k row 0..7
    const int bc = (tid & 15) * 8;    // B load: n col 0..120

    const float* Ap = A + (size_t)(row0 + ar) * lda + ak;
    const float* Bp = B + (size_t)br * ldb + col0 + bc;

    float4 pa  = *(const float4*)Ap;
    float4 pb0 = *(const float4*)Bp;
    float4 pb1 = *(const float4*)(Bp + 4);

    u64 acc[4][8];
#pragma unroll
    for (int p = 0; p < 4; p++)
#pragma unroll
        for (int j = 0; j < 8; j++) acc[p][j] = 0ull;

#pragma unroll 1
    for (int k0 = 0; k0 < 128; k0 += 8) {
        As[ak + 0][ar] = pa.x;
        As[ak + 1][ar] = pa.y;
        As[ak + 2][ar] = pa.z;
        As[ak + 3][ar] = pa.w;
        *(float4*)&Bs[br][bc]     = pb0;
        *(float4*)&Bs[br][bc + 4] = pb1;
        __syncthreads();

        if (k0 + 8 < 128) {
            pa  = *(const float4*)(Ap + k0 + 8);
            pb0 = *(const float4*)(Bp + (size_t)(k0 + 8) * ldb);
            pb1 = *(const float4*)(Bp + (size_t)(k0 + 8) * ldb + 4);
        }

#pragma unroll
        for (int kk = 0; kk < 8; kk++) {
            const ulonglong2 a01 = *(const ulonglong2*)&As[kk][ty * 8];
            const ulonglong2 a23 = *(const ulonglong2*)&As[kk][ty * 8 + 4];
            const float4 b0 = *(const float4*)&Bs[kk][tx * 8];
            const float4 b1 = *(const float4*)&Bs[kk][tx * 8 + 4];
            const float bsc[8] = {b0.x, b0.y, b0.z, b0.w, b1.x, b1.y, b1.z, b1.w};
#pragma unroll
            for (int j = 0; j < 8; j++) {
                const u64 bd = pack2(bsc[j], bsc[j]);
                acc[0][j] = fma2(a01.x, bd, acc[0][j]);
                acc[1][j] = fma2(a01.y, bd, acc[1][j]);
                acc[2][j] = fma2(a23.x, bd, acc[2][j]);
                acc[3][j] = fma2(a23.y, bd, acc[3][j]);
            }
        }
        __syncthreads();
    }

    // epilogue: acc[p][j] = (out[2p][j], out[2p+1][j]) for this thread's 8x8
    const int orow = row0 + ty * 8;
    const int ocol = col0 + tx * 8;
#pragma unroll
    for (int p = 0; p < 4; p++) {
        float2 u0 = unpack2(acc[p][0]);
        float2 u1 = unpack2(acc[p][1]);
        float2 u2 = unpack2(acc[p][2]);
        float2 u3 = unpack2(acc[p][3]);
        float2 u4 = unpack2(acc[p][4]);
        float2 u5 = unpack2(acc[p][5]);
        float2 u6 = unpack2(acc[p][6]);
        float2 u7 = unpack2(acc[p][7]);
        float* r0 = P + (size_t)(orow + 2 * p) * ldp + ocol;
        float* r1 = r0 + ldp;
        *(float4*)r0       = make_float4(u0.x, u1.x, u2.x, u3.x);
        *(float4*)(r0 + 4) = make_float4(u4.x, u5.x, u6.x, u7.x);
        *(float4*)r1       = make_float4(u0.y, u1.y, u2.y, u3.y);
        *(float4*)(r1 + 4) = make_float4(u4.y, u5.y, u6.y, u7.y);
    }
}

// Stage 1a: split-K partials for K = h1@w1 (which=0) and Q = h2@w2 (which=1).
// grid (2, 32, 8 = which*4+ks), block 128. Slab (ks,which): ks*2+which.
__global__ void __launch_bounds__(128, 4)
qk_gemm_split(const float* __restrict__ h1, const float* __restrict__ h2,
              const float* __restrict__ w)
{
    const int which = blockIdx.z >> 2;
    const int ks    = blockIdx.z & 3;
    const int k0    = ks * 128;
    const float* A  = (which ? h2 : h1) + k0;
    const float* Bm = w + (size_t)which * EE * UU + (size_t)k0 * UU;
    float* P = g_part + (size_t)(ks * 2 + which) * 2048 * 256;
    sgemm_64x128_k128(A, Bm, P, EE, UU, 256, blockIdx.y * 64, blockIdx.x * 128);
}

// Stage 1b: reduce partials -> g_K (+b1), g_Q. grid 1024, block 256.
__global__ void __launch_bounds__(256)
qk_reduce(const float* __restrict__ b1)
{
    const int t = blockIdx.x * 256 + threadIdx.x;
    const int which = t >> 17;
    const int i4 = t & 131071;
    const float4* p = (const float4*)g_part + (size_t)which * 131072 + i4;
    float4 s0 = p[0];
    float4 s1 = p[262144];
    float4 s2 = p[524288];
    float4 s3 = p[786432];
    float4 o = make_float4((s0.x + s1.x) + (s2.x + s3.x),
                           (s0.y + s1.y) + (s2.y + s3.y),
                           (s0.z + s1.z) + (s2.z + s3.z),
                           (s0.w + s1.w) + (s2.w + s3.w));
    if (which == 0) {
        const float4 bv = ((const float4*)b1)[i4 & 63];
        o.x += bv.x; o.y += bv.y; o.z += bv.z; o.w += bv.w;
        ((float4*)g_K)[i4] = o;
    } else {
        ((float4*)g_Q)[i4] = o;
    }
}

// Stage 3a: split-K partials for out[b] = P[b] @ h1[b].
// grid (4, 8, 16 = b*4+ks), block 128.
__global__ void __launch_bounds__(128, 4)
pv_gemm_split(const float* __restrict__ h1)
{
    const int b  = blockIdx.z >> 2;
    const int ks = blockIdx.z & 3;
    const int k0 = ks * 128;
    const float* A  = g_S + (size_t)b * SS * SS + k0;
    const float* Bm = h1  + (size_t)b * SS * EE + (size_t)k0 * EE;
    float* P = g_part + (size_t)ks * 2048 * 512 + (size_t)b * 512 * 512;
    sgemm_64x128_k128(A, Bm, P, SS, EE, 512, blockIdx.y * 64, blockIdx.x * 128);
}

// Stage 3b: reduce partials -> out. grid 1024, block 256.
__global__ void __launch_bounds__(256)
pv_reduce(float* __restrict__ out)
{
    const int i4 = blockIdx.x * 256 + threadIdx.x;
    const float4* p = (const float4*)g_part + i4;
    float4 s0 = p[0];
    float4 s1 = p[262144];
    float4 s2 = p[524288];
    float4 s3 = p[786432];
    ((float4*)out)[i4] = make_float4((s0.x + s1.x) + (s2.x + s3.x),
                                     (s0.y + s1.y) + (s2.y + s3.y),
                                     (s0.z + s1.z) + (s2.z + s3.z),
                                     (s0.w + s1.w) + (s2.w + s3.w));
}

// ---------------------------------------------------------------------------
// Stage 2: fused scores + softmax, register-resident (MUFU-floor bound).
// grid (64, 4), block 256.
// ---------------------------------------------------------------------------
__global__ void __launch_bounds__(256)
scores_softmax(const float* __restrict__ v)
{
    __shared__ __align__(16) float4 qs[8][64];
    __shared__ __align__(16) float4 vs[64];
    __shared__ __align__(16) float4 ks[2][32][33];

    const int it = blockIdx.x;
    const int b  = blockIdx.y;
    const int tid = threadIdx.x;
    const int w  = tid >> 5;
    const int jl = tid & 31;

    const float4* Q4 = (const float4*)g_Q + (size_t)(b * SS + it * 8) * 64;
    const float4* K4 = (const float4*)g_K + (size_t)(b * SS) * 64;

    ((float4*)qs)[tid]       = Q4[tid];
    ((float4*)qs)[tid + 256] = Q4[tid + 256];
    if (tid < 64) vs[tid] = ((const float4*)v)[tid];

    const int lc = tid & 31;
    const int lr = (tid >> 5) * 4;

#pragma unroll
    for (int i = 0; i < 4; i++)
        cp16(&ks[0][lr + i][lc], K4 + (size_t)(lr + i) * 64 + lc);
    asm volatile("cp.async.commit_group;");
#pragma unroll
    for (int i = 0; i < 4; i++)
        cp16(&ks[1][lr + i][lc], K4 + (size_t)(32 + lr + i) * 64 + lc);
    asm volatile("cp.async.commit_group;");

    float acc[16];
#pragma unroll
    for (int i = 0; i < 16; i++) acc[i] = 0.f;

#pragma unroll 1
    for (int s = 0; s < 32; s++) {
        if (s < 31) { asm volatile("cp.async.wait_group 1;"); }
        else        { asm volatile("cp.async.wait_group 0;"); }
        __syncthreads();

        const int uc = s >> 4, jc = s & 15;
        const float4* kp = &ks[s & 1][jl][0];
        const float4* qp = &qs[w][uc * 32];
        const float4* vp = &vs[uc * 32];
        float ax = 0.f, ay = 0.f, az = 0.f, aw = 0.f;
#pragma unroll
        for (int cc = 0; cc < 32; cc++) {
            const float4 kv = kp[cc];
            const float4 qv = qp[cc];
            const float4 vv = vp[cc];
            ax += vv.x * tanh_ap(qv.x + kv.x);
            ay += vv.y * tanh_ap(qv.y + kv.y);
            az += vv.z * tanh_ap(qv.z + kv.z);
            aw += vv.w * tanh_ap(qv.w + kv.w);
        }
        acc[jc] += (ax + ay) + (az + aw);
        __syncthreads();

        if (s < 30) {
            const int s2 = s + 2;
            const int jc2 = s2 & 15, uc2 = s2 >> 4;
#pragma unroll
            for (int i = 0; i < 4; i++)
                cp16(&ks[s & 1][lr + i][lc],
                     K4 + (size_t)(jc2 * 32 + lr + i) * 64 + uc2 * 32 + lc);
            asm volatile("cp.async.commit_group;");
        }
    }

    float m = acc[0];
#pragma unroll
    for (int i = 1; i < 16; i++) m = fmaxf(m, acc[i]);
#pragma unroll
    for (int o = 16; o > 0; o >>= 1)
        m = fmaxf(m, __shfl_xor_sync(0xffffffffu, m, o));

    const float L2E = 1.4426950408889634f;
    float sum = 0.f;
#pragma unroll
    for (int i = 0; i < 16; i++) {
        acc[i] = ex2_ap((acc[i] - m) * L2E);
        sum += acc[i];
    }
#pragma unroll
    for (int o = 16; o > 0; o >>= 1)
        sum += __shfl_xor_sync(0xffffffffu, sum, o);
    const float inv = 1.0f / sum;

    float* prow = g_S + (size_t)(b * SS + it * 8 + w) * SS + jl;
#pragma unroll
    for (int jc = 0; jc < 16; jc++)
        prow[jc * 32] = acc[jc] * inv;
}

extern "C" void kernel_launch(void* const* d_in, const int* in_sizes, int n_in,
                              void* d_out, int out_size)
{
    const float* h1 = (const float*)d_in[0];
    const float* h2 = (const float*)d_in[1];
    const float* w  = (const float*)d_in[2];
    const float* b1 = (const float*)d_in[3];
    const float* v  = (const float*)d_in[4];
    // b2 (d_in[5]) unused: softmax is shift-invariant.
    float* out = (float*)d_out;

    dim3 gA(UU / 128, (BB * SS) / 64, 2 * KSPLIT);  // (2, 32, 8) = 512 CTAs
    qk_gemm_split<<<gA, 128>>>(h1, h2, w);
    qk_reduce<<<1024, 256>>>(b1);

    dim3 gB(SS / 8, BB);                            // (64, 4) = 256 CTAs
    scores_softmax<<<gB, 256>>>(v);

    dim3 gD(EE / 128, SS / 64, BB * KSPLIT);        // (4, 8, 16) = 512 CTAs
    pv_gemm_split<<<gD, 128>>>(h1);
    pv_reduce<<<1024, 256>>>(out);
}